// round 16
// baseline (speedup 1.0000x reference)
#include <cuda_runtime.h>
#include <math.h>

// ---------------- problem constants ----------------
#define BB 64
#define HH 224
#define WW 224
#define CC 3
#define P1 109          // pooled1 spatial
#define C1 8
#define P2 52           // pooled2 spatial
#define C2 10
#define FLAT 27040      // 52*52*10

// fc1 split-K GEMM geometry: 520 chunks x 52 = 27040
#define NCHUNK 520
#define CK 52

// conv1 deinterleaved smem: [ic][row][col], row stride 44 (16B-aligned), plane 38*44
#define C1RS 44
#define C1PL (38 * C1RS)
// conv2 deinterleaved smem: [ic][row][col], row stride 72; 12 rows per plane
#define C2RS 72
#define C2PL (12 * C2RS)

// ---------------- scratch (static device globals; no allocs allowed) ---------
__device__ float g_pool1[BB * P1 * P1 * C1];   // ~24.3 MB
__device__ float g_pool2[BB * P2 * P2 * C2];   // ~6.9 MB
__device__ float g_fc_part[NCHUNK * BB * 32];  // 4.26 MB
__device__ float g_theta[BB * 6];

// ---------------- packed f32x2 helpers (sm_103a FFMA2) -----------------------
typedef unsigned long long u64;

__device__ __forceinline__ u64 pack_dup(float a) {
    u64 r;
    asm("mov.b64 %0, {%1, %1};" : "=l"(r) : "f"(a));
    return r;
}
__device__ __forceinline__ void fma2(u64& d, u64 a, u64 b) {
    // d = a * b + d, packed 2x fp32, round-to-nearest (exact fp32 numerics)
    asm("fma.rn.f32x2 %0, %1, %2, %0;" : "+l"(d) : "l"(a), "l"(b));
}
__device__ __forceinline__ void unpack2(u64 v, float& lo, float& hi) {
    asm("mov.b64 {%0, %1}, %2;" : "=f"(lo), "=f"(hi) : "l"(v));
}

// =============================================================================
// K1: conv 7x7x3->8 (VALID) + bias + relu + maxpool2, fused. (R13/R15 body)
// =============================================================================
__global__ __launch_bounds__(128) void conv1_pool_kernel(
    const float* __restrict__ in, const float* __restrict__ w,
    const float* __restrict__ bias)
{
    __shared__ __align__(16) float sh_in[3 * C1PL];     // 5016 floats
    __shared__ __align__(16) float sh_w[7 * 7 * 3 * 8]; // 1176

    const int b   = blockIdx.z;
    const int iy0 = blockIdx.y * 32;       // conv-row origin of tile
    const int ix0 = blockIdx.x * 32;       // conv-col origin of tile
    const int tx  = threadIdx.x;           // 0..7
    const int ty  = threadIdx.y;           // 0..15
    const int tid = ty * 8 + tx;

    for (int t = tid; t < 1176; t += 128) sh_w[t] = w[t];

    const float* inb = in + (size_t)b * HH * WW * CC;
    for (int t = tid; t < 38 * 114; t += 128) {
        int row = t / 114;
        int rem = t - row * 114;
        int col = rem / 3;
        int ic  = rem - col * 3;
        int gy = iy0 + row, gx = ix0 + col;
        float v = 0.f;
        if (gy < HH && gx < WW) v = inb[(gy * WW + gx) * 3 + ic];
        sh_in[ic * C1PL + row * C1RS + col] = v;    // coalesced read, scatter write
    }
    __syncthreads();

    u64 acc[8][4];   // [conv pixel: 4 of pooled0, 4 of pooled1][oc pair]
#pragma unroll
    for (int p = 0; p < 8; p++)
#pragma unroll
        for (int o = 0; o < 4; o++) acc[p][o] = 0ull;

    const int ry = 2 * ty;
    const int rx = 4 * tx;

    for (int kh = 0; kh < 7; kh++) {
#pragma unroll
        for (int ic = 0; ic < 3; ic++) {
            const float* r0 = &sh_in[ic * C1PL + (ry + kh) * C1RS + rx];
            const float* r1 = r0 + C1RS;
            float4 q0a = *(const float4*)(r0);
            float4 q0b = *(const float4*)(r0 + 4);
            float2 q0c = *(const float2*)(r0 + 8);
            float4 q1a = *(const float4*)(r1);
            float4 q1b = *(const float4*)(r1 + 4);
            float2 q1c = *(const float2*)(r1 + 8);
            u64 a0[10], a1[10];
            a0[0] = pack_dup(q0a.x); a0[1] = pack_dup(q0a.y);
            a0[2] = pack_dup(q0a.z); a0[3] = pack_dup(q0a.w);
            a0[4] = pack_dup(q0b.x); a0[5] = pack_dup(q0b.y);
            a0[6] = pack_dup(q0b.z); a0[7] = pack_dup(q0b.w);
            a0[8] = pack_dup(q0c.x); a0[9] = pack_dup(q0c.y);
            a1[0] = pack_dup(q1a.x); a1[1] = pack_dup(q1a.y);
            a1[2] = pack_dup(q1a.z); a1[3] = pack_dup(q1a.w);
            a1[4] = pack_dup(q1b.x); a1[5] = pack_dup(q1b.y);
            a1[6] = pack_dup(q1b.z); a1[7] = pack_dup(q1b.w);
            a1[8] = pack_dup(q1c.x); a1[9] = pack_dup(q1c.y);
#pragma unroll
            for (int kw = 0; kw < 7; kw++) {
                const u64* wp = (const u64*)&sh_w[(kh * 7 + kw) * 24 + ic * 8];
#pragma unroll
                for (int o = 0; o < 4; o++) {
                    u64 wv = wp[o];
                    fma2(acc[0][o], a0[kw],     wv);
                    fma2(acc[1][o], a0[kw + 1], wv);
                    fma2(acc[2][o], a1[kw],     wv);
                    fma2(acc[3][o], a1[kw + 1], wv);
                    fma2(acc[4][o], a0[kw + 2], wv);
                    fma2(acc[5][o], a0[kw + 3], wv);
                    fma2(acc[6][o], a1[kw + 2], wv);
                    fma2(acc[7][o], a1[kw + 3], wv);
                }
            }
        }
    }

    const int py  = blockIdx.y * 16 + ty;
    const int px0 = blockIdx.x * 16 + 2 * tx;
    if (py < P1) {
#pragma unroll
        for (int pp = 0; pp < 2; pp++) {
            int px = px0 + pp;
            if (px < P1) {
                float* op = &g_pool1[((b * P1 + py) * P1 + px) * C1];
                int base = pp * 4;
#pragma unroll
                for (int o = 0; o < 4; o++) {
                    float a0f, a1f, b0f, b1f, c0f, c1f, d0f, d1f;
                    unpack2(acc[base + 0][o], a0f, a1f);
                    unpack2(acc[base + 1][o], b0f, b1f);
                    unpack2(acc[base + 2][o], c0f, c1f);
                    unpack2(acc[base + 3][o], d0f, d1f);
                    // max(relu(x_i + b)) == relu(max(x_i) + b)  (relu monotone)
                    float m0 = fmaxf(fmaxf(a0f, b0f), fmaxf(c0f, d0f));
                    float m1 = fmaxf(fmaxf(a1f, b1f), fmaxf(c1f, d1f));
                    op[2 * o]     = fmaxf(m0 + bias[2 * o], 0.f);
                    op[2 * o + 1] = fmaxf(m1 + bias[2 * o + 1], 0.f);
                }
            }
        }
    }
}

// =============================================================================
// K2: conv 5x5x8->10 (VALID) + bias + relu + maxpool2, fused. Input = g_pool1.
// FINE-GRAINED TILES to kill wave quantization: pooled tile 32x4, block
// (16,4)=64 thr (2 dense warps), grid (2,13,64)=1664, 6 blocks/SM -> 1.87
// waves (was 896 blocks @ 3/SM = 2.02 waves -> 3 generations, measured 88us
// = 3 x 29.3; ideal 59). Inner loop identical to the benched R13 body.
// =============================================================================
__global__ __launch_bounds__(64) void conv2_pool_kernel(
    const float* __restrict__ w, const float* __restrict__ bias)
{
    extern __shared__ float dsm[];
    float* sh_in = dsm;            // [ic]: ic*C2PL + row*C2RS + col ; 8*864=6912
    float* sh_w  = dsm + 6912;     // 2000 floats; offset 27648B -> 16B aligned

    const int b   = blockIdx.z;
    const int iy0 = blockIdx.y * 8;      // conv-row origin (4 pooled rows)
    const int ix0 = blockIdx.x * 64;     // conv-col origin
    const int tx  = threadIdx.x;         // 0..15
    const int ty  = threadIdx.y;         // 0..3
    const int tid = ty * 16 + tx;

    for (int t = tid; t < 2000; t += 64) sh_w[t] = w[t];

    const float* inb = g_pool1 + (size_t)b * P1 * P1 * C1;
    for (int t = tid; t < 12 * 68 * 8; t += 64) {
        int ic  = t & 7;
        int col = (t >> 3) % 68;
        int row = t / (68 * 8);
        int gy = iy0 + row, gx = ix0 + col;
        float v = 0.f;
        if (gy < P1 && gx < P1) v = inb[(gy * P1 + gx) * 8 + ic];
        sh_in[ic * C2PL + row * C2RS + col] = v;
    }
    __syncthreads();

    u64 acc[8][5];   // [conv pixel][oc pair]
#pragma unroll
    for (int p = 0; p < 8; p++)
#pragma unroll
        for (int o = 0; o < 5; o++) acc[p][o] = 0ull;

    const int ry = 2 * ty;
    const int rx = 4 * tx;

    for (int kh = 0; kh < 5; kh++) {
#pragma unroll
        for (int ic = 0; ic < 8; ic++) {
            const float* r0 = &sh_in[ic * C2PL + (ry + kh) * C2RS + rx];
            const float* r1 = r0 + C2RS;
            float4 q0a = *(const float4*)(r0);
            float4 q0b = *(const float4*)(r0 + 4);
            float4 q1a = *(const float4*)(r1);
            float4 q1b = *(const float4*)(r1 + 4);
            u64 a0[8], a1[8];
            a0[0] = pack_dup(q0a.x); a0[1] = pack_dup(q0a.y);
            a0[2] = pack_dup(q0a.z); a0[3] = pack_dup(q0a.w);
            a0[4] = pack_dup(q0b.x); a0[5] = pack_dup(q0b.y);
            a0[6] = pack_dup(q0b.z); a0[7] = pack_dup(q0b.w);
            a1[0] = pack_dup(q1a.x); a1[1] = pack_dup(q1a.y);
            a1[2] = pack_dup(q1a.z); a1[3] = pack_dup(q1a.w);
            a1[4] = pack_dup(q1b.x); a1[5] = pack_dup(q1b.y);
            a1[6] = pack_dup(q1b.z); a1[7] = pack_dup(q1b.w);
#pragma unroll
            for (int kw = 0; kw < 5; kw++) {
                const u64* wq = (const u64*)&sh_w[(kh * 5 + kw) * 80 + ic * 10];
#pragma unroll
                for (int o = 0; o < 5; o++) {
                    u64 wv = wq[o];
                    fma2(acc[0][o], a0[kw],     wv);
                    fma2(acc[1][o], a0[kw + 1], wv);
                    fma2(acc[2][o], a1[kw],     wv);
                    fma2(acc[3][o], a1[kw + 1], wv);
                    fma2(acc[4][o], a0[kw + 2], wv);
                    fma2(acc[5][o], a0[kw + 3], wv);
                    fma2(acc[6][o], a1[kw + 2], wv);
                    fma2(acc[7][o], a1[kw + 3], wv);
                }
            }
        }
    }

    const int py  = blockIdx.y * 4 + ty;          // 13*4 = 52 exact, py < P2 always
    const int px0 = blockIdx.x * 32 + 2 * tx;
#pragma unroll
    for (int pp = 0; pp < 2; pp++) {
        int px = px0 + pp;
        if (px < P2) {
            float* op = &g_pool2[((b * P2 + py) * P2 + px) * C2];
            int base = pp * 4;
#pragma unroll
            for (int o = 0; o < 5; o++) {
                float a0f, a1f, b0f, b1f, c0f, c1f, d0f, d1f;
                unpack2(acc[base + 0][o], a0f, a1f);
                unpack2(acc[base + 1][o], b0f, b1f);
                unpack2(acc[base + 2][o], c0f, c1f);
                unpack2(acc[base + 3][o], d0f, d1f);
                float m0 = fmaxf(fmaxf(a0f, b0f), fmaxf(c0f, d0f));
                float m1 = fmaxf(fmaxf(a1f, b1f), fmaxf(c1f, d1f));
                op[2 * o]     = fmaxf(m0 + bias[2 * o], 0.f);
                op[2 * o + 1] = fmaxf(m1 + bias[2 * o + 1], 0.f);
            }
        }
    }
}

// =============================================================================
// K3a: fc1 as split-K GEMM, 520 chunks of CK=52. (R15-benched)
// =============================================================================
__global__ __launch_bounds__(256) void fc1_gemm_kernel(const float* __restrict__ w1)
{
    extern __shared__ float sm[];
    float* sw = sm;             // [CK][32]   1664 floats
    float* sx = sm + CK * 32;   // [64][CK]   3328 floats

    const int chunk = blockIdx.x;
    const int k0 = chunk * CK;
    const int tid = threadIdx.x;

    for (int t = tid; t < CK * 32; t += 256) sw[t] = w1[(size_t)k0 * 32 + t];
    for (int t = tid; t < BB * CK; t += 256) {
        int b = t / CK;
        int k = t - b * CK;
        sx[t] = g_pool2[(size_t)b * FLAT + k0 + k];
    }
    __syncthreads();

    const int ogrp = tid & 7;     // owns outputs ogrp*4 .. ogrp*4+3
    const int bgrp = tid >> 3;    // owns batches bgrp*2, bgrp*2+1

    const float* x0p = &sx[(bgrp * 2) * CK];
    const float* x1p = x0p + CK;
    const float4* wp = (const float4*)&sw[ogrp * 4];   // stride 8 float4 per k

    float acc0[4] = {0.f, 0.f, 0.f, 0.f};
    float acc1[4] = {0.f, 0.f, 0.f, 0.f};

#pragma unroll 4
    for (int k = 0; k < CK; k++) {
        float4 wv = wp[k * 8];
        float x0 = x0p[k];
        float x1 = x1p[k];
        acc0[0] = fmaf(x0, wv.x, acc0[0]);
        acc0[1] = fmaf(x0, wv.y, acc0[1]);
        acc0[2] = fmaf(x0, wv.z, acc0[2]);
        acc0[3] = fmaf(x0, wv.w, acc0[3]);
        acc1[0] = fmaf(x1, wv.x, acc1[0]);
        acc1[1] = fmaf(x1, wv.y, acc1[1]);
        acc1[2] = fmaf(x1, wv.z, acc1[2]);
        acc1[3] = fmaf(x1, wv.w, acc1[3]);
    }

    float* op = &g_fc_part[((size_t)chunk * BB + bgrp * 2) * 32 + ogrp * 4];
    *(float4*)op        = make_float4(acc0[0], acc0[1], acc0[2], acc0[3]);
    *(float4*)(op + 32) = make_float4(acc1[0], acc1[1], acc1[2], acc1[3]);
}

// =============================================================================
// K3b: reduce 520 chunk-partials, bias+relu, then fc2 -> theta.
// WIDENED: block 1024 (32 warp-groups) -> 4x latency hiding vs 256
// (measured 8.3us at occ 9.9%, issue 11.3%). Group g sums chunks g, g+32, ...
// =============================================================================
__global__ __launch_bounds__(1024) void fc2_kernel(
    const float* __restrict__ b1, const float* __restrict__ w2,
    const float* __restrict__ b2)
{
    const int b    = blockIdx.x;
    const int tid  = threadIdx.x;
    const int o    = tid & 31;
    const int grp  = tid >> 5;     // 0..31

    float s = 0.f;
#pragma unroll
    for (int j = 0; j < 17; j++) {
        int c = grp + 32 * j;
        if (c < NCHUNK)
            s += g_fc_part[((size_t)c * BB + b) * 32 + o];
    }

    __shared__ float red[32][33];
    __shared__ float sh_h1[32];
    red[grp][o] = s;
    __syncthreads();

    if (grp == 0) {
        float t = red[0][o];
#pragma unroll
        for (int k = 1; k < 32; k++) t += red[k][o];
        sh_h1[o] = fmaxf(t + b1[o], 0.f);
        __syncwarp();
        if (o < 6) {
            float th = b2[o];
#pragma unroll
            for (int k = 0; k < 32; k++)
                th = fmaf(sh_h1[k], w2[k * 6 + o], th);
            g_theta[b * 6 + o] = th;
        }
    }
}

// =============================================================================
// K4: affine grid + bilinear sampler. (unchanged, PB-benched)
// =============================================================================
__global__ __launch_bounds__(256) void sampler_kernel(
    const float* __restrict__ in, float* __restrict__ out)
{
    const int pix_per_img = HH * WW;           // 50176
    const int blocks_per_img = pix_per_img / 256;
    const int b = blockIdx.x / blocks_per_img;

    __shared__ float th[6];
    if (threadIdx.x < 6) th[threadIdx.x] = g_theta[b * 6 + threadIdx.x];
    __syncthreads();

    const int idx = blockIdx.x * 256 + threadIdx.x;
    const int rem = idx - b * pix_per_img;
    const int i = rem / WW;
    const int j = rem - i * WW;

    const float step = 2.0f / 223.0f;
    float xt = fmaf((float)j, step, -1.0f);
    float yt = fmaf((float)i, step, -1.0f);

    float xs = th[0] * xt + th[1] * yt + th[2];
    float ys = th[3] * xt + th[4] * yt + th[5];

    float x = 0.5f * (xs + 1.0f) * 223.0f;
    float y = 0.5f * (ys + 1.0f) * 223.0f;

    int x0 = min(max((int)floorf(x), 0), 223);
    int x1 = min(x0 + 1, 223);
    int y0 = min(max((int)floorf(y), 0), 223);
    int y1 = min(y0 + 1, 223);

    float x0f = (float)x0, x1f = (float)x1;
    float y0f = (float)y0, y1f = (float)y1;
    float wa = (x1f - x) * (y1f - y);
    float wb = (x1f - x) * (y - y0f);
    float wc = (x - x0f) * (y1f - y);
    float wd = (x - x0f) * (y - y0f);

    const float* base = in + (size_t)b * HH * WW * 3;
    const float* pa  = base + (y0 * WW + x0) * 3;
    const float* pbp = base + (y1 * WW + x0) * 3;
    const float* pc  = base + (y0 * WW + x1) * 3;
    const float* pd  = base + (y1 * WW + x1) * 3;

    float* op = out + (size_t)idx * 3;
#pragma unroll
    for (int c = 0; c < 3; c++) {
        op[c] = wa * pa[c] + wb * pbp[c] + wc * pc[c] + wd * pd[c];
    }
}

// =============================================================================
extern "C" void kernel_launch(void* const* d_in, const int* in_sizes, int n_in,
                              void* d_out, int out_size)
{
    const float* in  = (const float*)d_in[0];
    const float* c1w = (const float*)d_in[1];
    const float* c1b = (const float*)d_in[2];
    const float* c2w = (const float*)d_in[3];
    const float* c2b = (const float*)d_in[4];
    const float* f1w = (const float*)d_in[5];
    const float* f1b = (const float*)d_in[6];
    const float* f2w = (const float*)d_in[7];
    const float* f2b = (const float*)d_in[8];
    float* out = (float*)d_out;

    const int conv2_smem = (8 * C2PL + 2000) * 4;       // 35648 B
    const int fc1_smem   = (CK * 32 + BB * CK) * 4;     // 19968 B
    cudaFuncSetAttribute(conv2_pool_kernel,
                         cudaFuncAttributeMaxDynamicSharedMemorySize, conv2_smem);

    conv1_pool_kernel<<<dim3(7, 7, BB), dim3(8, 16)>>>(in, c1w, c1b);
    conv2_pool_kernel<<<dim3(2, 13, BB), dim3(16, 4), conv2_smem>>>(c2w, c2b);
    fc1_gemm_kernel<<<NCHUNK, 256, fc1_smem>>>(f1w);
    fc2_kernel<<<BB, 1024>>>(f1b, f2w, f2b);
    sampler_kernel<<<(BB * HH * WW) / 256, 256>>>(in, out);
}

// round 17
// speedup vs baseline: 1.0113x; 1.0113x over previous
#include <cuda_runtime.h>
#include <math.h>

// ---------------- problem constants ----------------
#define BB 64
#define HH 224
#define WW 224
#define CC 3
#define P1 109          // pooled1 spatial
#define C1 8
#define P2 52           // pooled2 spatial
#define C2 10
#define FLAT 27040      // 52*52*10

// fc1 split-K GEMM geometry: 520 chunks x 52 = 27040
#define NCHUNK 520
#define CK 52

// conv1 deinterleaved smem: [ic][row][col], row stride 44 (16B-aligned), plane 38*44
#define C1RS 44
#define C1PL (38 * C1RS)
// conv2 deinterleaved smem: [ic][row][col], row stride 72, plane padded to 1448
#define C2RS 72
#define C2PL 1448

// ---------------- scratch (static device globals; no allocs allowed) ---------
__device__ float g_pool1[BB * P1 * P1 * C1];   // ~24.3 MB
__device__ float g_pool2[BB * P2 * P2 * C2];   // ~6.9 MB
__device__ float g_fc_part[NCHUNK * BB * 32];  // 4.26 MB
__device__ float g_theta[BB * 6];

// ---------------- packed f32x2 helpers (sm_103a FFMA2) -----------------------
typedef unsigned long long u64;

__device__ __forceinline__ u64 pack_dup(float a) {
    u64 r;
    asm("mov.b64 %0, {%1, %1};" : "=l"(r) : "f"(a));
    return r;
}
__device__ __forceinline__ void fma2(u64& d, u64 a, u64 b) {
    // d = a * b + d, packed 2x fp32, round-to-nearest (exact fp32 numerics)
    asm("fma.rn.f32x2 %0, %1, %2, %0;" : "+l"(d) : "l"(a), "l"(b));
}
__device__ __forceinline__ void unpack2(u64 v, float& lo, float& hi) {
    asm("mov.b64 {%0, %1}, %2;" : "=f"(lo), "=f"(hi) : "l"(v));
}

// =============================================================================
// K1: conv 7x7x3->8 (VALID) + bias + relu + maxpool2, fused. (PB-benched body)
// =============================================================================
__global__ __launch_bounds__(128) void conv1_pool_kernel(
    const float* __restrict__ in, const float* __restrict__ w,
    const float* __restrict__ bias)
{
    __shared__ __align__(16) float sh_in[3 * C1PL];     // 5016 floats
    __shared__ __align__(16) float sh_w[7 * 7 * 3 * 8]; // 1176

    const int b   = blockIdx.z;
    const int iy0 = blockIdx.y * 32;       // conv-row origin of tile
    const int ix0 = blockIdx.x * 32;       // conv-col origin of tile
    const int tx  = threadIdx.x;           // 0..7
    const int ty  = threadIdx.y;           // 0..15
    const int tid = ty * 8 + tx;

    for (int t = tid; t < 1176; t += 128) sh_w[t] = w[t];

    const float* inb = in + (size_t)b * HH * WW * CC;
    for (int t = tid; t < 38 * 114; t += 128) {
        int row = t / 114;
        int rem = t - row * 114;
        int col = rem / 3;
        int ic  = rem - col * 3;
        int gy = iy0 + row, gx = ix0 + col;
        float v = 0.f;
        if (gy < HH && gx < WW) v = inb[(gy * WW + gx) * 3 + ic];
        sh_in[ic * C1PL + row * C1RS + col] = v;    // coalesced read, scatter write
    }
    __syncthreads();

    u64 acc[8][4];   // [conv pixel: 4 of pooled0, 4 of pooled1][oc pair]
#pragma unroll
    for (int p = 0; p < 8; p++)
#pragma unroll
        for (int o = 0; o < 4; o++) acc[p][o] = 0ull;

    const int ry = 2 * ty;
    const int rx = 4 * tx;

    for (int kh = 0; kh < 7; kh++) {
#pragma unroll
        for (int ic = 0; ic < 3; ic++) {
            const float* r0 = &sh_in[ic * C1PL + (ry + kh) * C1RS + rx];
            const float* r1 = r0 + C1RS;
            float4 q0a = *(const float4*)(r0);
            float4 q0b = *(const float4*)(r0 + 4);
            float2 q0c = *(const float2*)(r0 + 8);
            float4 q1a = *(const float4*)(r1);
            float4 q1b = *(const float4*)(r1 + 4);
            float2 q1c = *(const float2*)(r1 + 8);
            u64 a0[10], a1[10];
            a0[0] = pack_dup(q0a.x); a0[1] = pack_dup(q0a.y);
            a0[2] = pack_dup(q0a.z); a0[3] = pack_dup(q0a.w);
            a0[4] = pack_dup(q0b.x); a0[5] = pack_dup(q0b.y);
            a0[6] = pack_dup(q0b.z); a0[7] = pack_dup(q0b.w);
            a0[8] = pack_dup(q0c.x); a0[9] = pack_dup(q0c.y);
            a1[0] = pack_dup(q1a.x); a1[1] = pack_dup(q1a.y);
            a1[2] = pack_dup(q1a.z); a1[3] = pack_dup(q1a.w);
            a1[4] = pack_dup(q1b.x); a1[5] = pack_dup(q1b.y);
            a1[6] = pack_dup(q1b.z); a1[7] = pack_dup(q1b.w);
            a1[8] = pack_dup(q1c.x); a1[9] = pack_dup(q1c.y);
#pragma unroll
            for (int kw = 0; kw < 7; kw++) {
                const u64* wp = (const u64*)&sh_w[(kh * 7 + kw) * 24 + ic * 8];
#pragma unroll
                for (int o = 0; o < 4; o++) {
                    u64 wv = wp[o];
                    fma2(acc[0][o], a0[kw],     wv);
                    fma2(acc[1][o], a0[kw + 1], wv);
                    fma2(acc[2][o], a1[kw],     wv);
                    fma2(acc[3][o], a1[kw + 1], wv);
                    fma2(acc[4][o], a0[kw + 2], wv);
                    fma2(acc[5][o], a0[kw + 3], wv);
                    fma2(acc[6][o], a1[kw + 2], wv);
                    fma2(acc[7][o], a1[kw + 3], wv);
                }
            }
        }
    }

    const int py  = blockIdx.y * 16 + ty;
    const int px0 = blockIdx.x * 16 + 2 * tx;
    if (py < P1) {
#pragma unroll
        for (int pp = 0; pp < 2; pp++) {
            int px = px0 + pp;
            if (px < P1) {
                float* op = &g_pool1[((b * P1 + py) * P1 + px) * C1];
                int base = pp * 4;
#pragma unroll
                for (int o = 0; o < 4; o++) {
                    float a0f, a1f, b0f, b1f, c0f, c1f, d0f, d1f;
                    unpack2(acc[base + 0][o], a0f, a1f);
                    unpack2(acc[base + 1][o], b0f, b1f);
                    unpack2(acc[base + 2][o], c0f, c1f);
                    unpack2(acc[base + 3][o], d0f, d1f);
                    // max(relu(x_i + b)) == relu(max(x_i) + b)  (relu monotone)
                    float m0 = fmaxf(fmaxf(a0f, b0f), fmaxf(c0f, d0f));
                    float m1 = fmaxf(fmaxf(a1f, b1f), fmaxf(c1f, d1f));
                    op[2 * o]     = fmaxf(m0 + bias[2 * o], 0.f);
                    op[2 * o + 1] = fmaxf(m1 + bias[2 * o + 1], 0.f);
                }
            }
        }
    }
}

// =============================================================================
// K2: conv 5x5x8->10 (VALID) + bias + relu + maxpool2, fused. Input = g_pool1.
// (PB-benched R15 form: block (16,8)=128 thr, pooled tile 32x8, grid (2,7,64).)
// =============================================================================
__global__ __launch_bounds__(128) void conv2_pool_kernel(
    const float* __restrict__ w, const float* __restrict__ bias)
{
    extern __shared__ float dsm[];
    float* sh_in = dsm;            // [ic]: ic*C2PL + row*C2RS + col ; 8*1448=11584
    float* sh_w  = dsm + 11584;    // 2000 floats; offset 46336B -> 16B aligned

    const int b   = blockIdx.z;
    const int iy0 = blockIdx.y * 16;     // conv-row origin
    const int ix0 = blockIdx.x * 64;     // conv-col origin
    const int tx  = threadIdx.x;         // 0..15
    const int ty  = threadIdx.y;         // 0..7
    const int tid = ty * 16 + tx;

    for (int t = tid; t < 2000; t += 128) sh_w[t] = w[t];

    const float* inb = g_pool1 + (size_t)b * P1 * P1 * C1;
    for (int t = tid; t < 20 * 68 * 8; t += 128) {
        int ic  = t & 7;
        int col = (t >> 3) % 68;
        int row = t / (68 * 8);
        int gy = iy0 + row, gx = ix0 + col;
        float v = 0.f;
        if (gy < P1 && gx < P1) v = inb[(gy * P1 + gx) * 8 + ic];
        sh_in[ic * C2PL + row * C2RS + col] = v;
    }
    __syncthreads();

    u64 acc[8][5];   // [conv pixel][oc pair]
#pragma unroll
    for (int p = 0; p < 8; p++)
#pragma unroll
        for (int o = 0; o < 5; o++) acc[p][o] = 0ull;

    const int ry = 2 * ty;
    const int rx = 4 * tx;

    for (int kh = 0; kh < 5; kh++) {
#pragma unroll
        for (int ic = 0; ic < 8; ic++) {
            const float* r0 = &sh_in[ic * C2PL + (ry + kh) * C2RS + rx];
            const float* r1 = r0 + C2RS;
            float4 q0a = *(const float4*)(r0);
            float4 q0b = *(const float4*)(r0 + 4);
            float4 q1a = *(const float4*)(r1);
            float4 q1b = *(const float4*)(r1 + 4);
            u64 a0[8], a1[8];
            a0[0] = pack_dup(q0a.x); a0[1] = pack_dup(q0a.y);
            a0[2] = pack_dup(q0a.z); a0[3] = pack_dup(q0a.w);
            a0[4] = pack_dup(q0b.x); a0[5] = pack_dup(q0b.y);
            a0[6] = pack_dup(q0b.z); a0[7] = pack_dup(q0b.w);
            a1[0] = pack_dup(q1a.x); a1[1] = pack_dup(q1a.y);
            a1[2] = pack_dup(q1a.z); a1[3] = pack_dup(q1a.w);
            a1[4] = pack_dup(q1b.x); a1[5] = pack_dup(q1b.y);
            a1[6] = pack_dup(q1b.z); a1[7] = pack_dup(q1b.w);
#pragma unroll
            for (int kw = 0; kw < 5; kw++) {
                const u64* wq = (const u64*)&sh_w[(kh * 5 + kw) * 80 + ic * 10];
#pragma unroll
                for (int o = 0; o < 5; o++) {
                    u64 wv = wq[o];
                    fma2(acc[0][o], a0[kw],     wv);
                    fma2(acc[1][o], a0[kw + 1], wv);
                    fma2(acc[2][o], a1[kw],     wv);
                    fma2(acc[3][o], a1[kw + 1], wv);
                    fma2(acc[4][o], a0[kw + 2], wv);
                    fma2(acc[5][o], a0[kw + 3], wv);
                    fma2(acc[6][o], a1[kw + 2], wv);
                    fma2(acc[7][o], a1[kw + 3], wv);
                }
            }
        }
    }

    const int py  = blockIdx.y * 8 + ty;
    const int px0 = blockIdx.x * 32 + 2 * tx;
    if (py < P2) {
#pragma unroll
        for (int pp = 0; pp < 2; pp++) {
            int px = px0 + pp;
            if (px < P2) {
                float* op = &g_pool2[((b * P2 + py) * P2 + px) * C2];
                int base = pp * 4;
#pragma unroll
                for (int o = 0; o < 5; o++) {
                    float a0f, a1f, b0f, b1f, c0f, c1f, d0f, d1f;
                    unpack2(acc[base + 0][o], a0f, a1f);
                    unpack2(acc[base + 1][o], b0f, b1f);
                    unpack2(acc[base + 2][o], c0f, c1f);
                    unpack2(acc[base + 3][o], d0f, d1f);
                    float m0 = fmaxf(fmaxf(a0f, b0f), fmaxf(c0f, d0f));
                    float m1 = fmaxf(fmaxf(a1f, b1f), fmaxf(c1f, d1f));
                    op[2 * o]     = fmaxf(m0 + bias[2 * o], 0.f);
                    op[2 * o + 1] = fmaxf(m1 + bias[2 * o + 1], 0.f);
                }
            }
        }
    }
}

// =============================================================================
// K3a: fc1 as split-K GEMM, 520 chunks of CK=52. (PB-benched)
// =============================================================================
__global__ __launch_bounds__(256) void fc1_gemm_kernel(const float* __restrict__ w1)
{
    extern __shared__ float sm[];
    float* sw = sm;             // [CK][32]   1664 floats
    float* sx = sm + CK * 32;   // [64][CK]   3328 floats

    const int chunk = blockIdx.x;
    const int k0 = chunk * CK;
    const int tid = threadIdx.x;

    for (int t = tid; t < CK * 32; t += 256) sw[t] = w1[(size_t)k0 * 32 + t];
    for (int t = tid; t < BB * CK; t += 256) {
        int b = t / CK;
        int k = t - b * CK;
        sx[t] = g_pool2[(size_t)b * FLAT + k0 + k];
    }
    __syncthreads();

    const int ogrp = tid & 7;     // owns outputs ogrp*4 .. ogrp*4+3
    const int bgrp = tid >> 3;    // owns batches bgrp*2, bgrp*2+1

    const float* x0p = &sx[(bgrp * 2) * CK];
    const float* x1p = x0p + CK;
    const float4* wp = (const float4*)&sw[ogrp * 4];   // stride 8 float4 per k

    float acc0[4] = {0.f, 0.f, 0.f, 0.f};
    float acc1[4] = {0.f, 0.f, 0.f, 0.f};

#pragma unroll 4
    for (int k = 0; k < CK; k++) {
        float4 wv = wp[k * 8];
        float x0 = x0p[k];
        float x1 = x1p[k];
        acc0[0] = fmaf(x0, wv.x, acc0[0]);
        acc0[1] = fmaf(x0, wv.y, acc0[1]);
        acc0[2] = fmaf(x0, wv.z, acc0[2]);
        acc0[3] = fmaf(x0, wv.w, acc0[3]);
        acc1[0] = fmaf(x1, wv.x, acc1[0]);
        acc1[1] = fmaf(x1, wv.y, acc1[1]);
        acc1[2] = fmaf(x1, wv.z, acc1[2]);
        acc1[3] = fmaf(x1, wv.w, acc1[3]);
    }

    float* op = &g_fc_part[((size_t)chunk * BB + bgrp * 2) * 32 + ogrp * 4];
    *(float4*)op        = make_float4(acc0[0], acc0[1], acc0[2], acc0[3]);
    *(float4*)(op + 32) = make_float4(acc1[0], acc1[1], acc1[2], acc1[3]);
}

// =============================================================================
// K3b: reduce 520 chunk-partials, bias+relu, then fc2 -> theta.
// (R16-benched: block 1024, 32 warp-groups; measured 6.6us vs 8.3 @ 256.)
// =============================================================================
__global__ __launch_bounds__(1024) void fc2_kernel(
    const float* __restrict__ b1, const float* __restrict__ w2,
    const float* __restrict__ b2)
{
    const int b    = blockIdx.x;
    const int tid  = threadIdx.x;
    const int o    = tid & 31;
    const int grp  = tid >> 5;     // 0..31

    float s = 0.f;
#pragma unroll
    for (int j = 0; j < 17; j++) {
        int c = grp + 32 * j;
        if (c < NCHUNK)
            s += g_fc_part[((size_t)c * BB + b) * 32 + o];
    }

    __shared__ float red[32][33];
    __shared__ float sh_h1[32];
    red[grp][o] = s;
    __syncthreads();

    if (grp == 0) {
        float t = red[0][o];
#pragma unroll
        for (int k = 1; k < 32; k++) t += red[k][o];
        sh_h1[o] = fmaxf(t + b1[o], 0.f);
        __syncwarp();
        if (o < 6) {
            float th = b2[o];
#pragma unroll
            for (int k = 0; k < 32; k++)
                th = fmaf(sh_h1[k], w2[k * 6 + o], th);
            g_theta[b * 6 + o] = th;
        }
    }
}

// =============================================================================
// K4: affine grid + bilinear sampler. (PB-benched)
// =============================================================================
__global__ __launch_bounds__(256) void sampler_kernel(
    const float* __restrict__ in, float* __restrict__ out)
{
    const int pix_per_img = HH * WW;           // 50176
    const int blocks_per_img = pix_per_img / 256;
    const int b = blockIdx.x / blocks_per_img;

    __shared__ float th[6];
    if (threadIdx.x < 6) th[threadIdx.x] = g_theta[b * 6 + threadIdx.x];
    __syncthreads();

    const int idx = blockIdx.x * 256 + threadIdx.x;
    const int rem = idx - b * pix_per_img;
    const int i = rem / WW;
    const int j = rem - i * WW;

    const float step = 2.0f / 223.0f;
    float xt = fmaf((float)j, step, -1.0f);
    float yt = fmaf((float)i, step, -1.0f);

    float xs = th[0] * xt + th[1] * yt + th[2];
    float ys = th[3] * xt + th[4] * yt + th[5];

    float x = 0.5f * (xs + 1.0f) * 223.0f;
    float y = 0.5f * (ys + 1.0f) * 223.0f;

    int x0 = min(max((int)floorf(x), 0), 223);
    int x1 = min(x0 + 1, 223);
    int y0 = min(max((int)floorf(y), 0), 223);
    int y1 = min(y0 + 1, 223);

    float x0f = (float)x0, x1f = (float)x1;
    float y0f = (float)y0, y1f = (float)y1;
    float wa = (x1f - x) * (y1f - y);
    float wb = (x1f - x) * (y - y0f);
    float wc = (x - x0f) * (y1f - y);
    float wd = (x - x0f) * (y - y0f);

    const float* base = in + (size_t)b * HH * WW * 3;
    const float* pa  = base + (y0 * WW + x0) * 3;
    const float* pbp = base + (y1 * WW + x0) * 3;
    const float* pc  = base + (y0 * WW + x1) * 3;
    const float* pd  = base + (y1 * WW + x1) * 3;

    float* op = out + (size_t)idx * 3;
#pragma unroll
    for (int c = 0; c < 3; c++) {
        op[c] = wa * pa[c] + wb * pbp[c] + wc * pc[c] + wd * pd[c];
    }
}

// =============================================================================
extern "C" void kernel_launch(void* const* d_in, const int* in_sizes, int n_in,
                              void* d_out, int out_size)
{
    const float* in  = (const float*)d_in[0];
    const float* c1w = (const float*)d_in[1];
    const float* c1b = (const float*)d_in[2];
    const float* c2w = (const float*)d_in[3];
    const float* c2b = (const float*)d_in[4];
    const float* f1w = (const float*)d_in[5];
    const float* f1b = (const float*)d_in[6];
    const float* f2w = (const float*)d_in[7];
    const float* f2b = (const float*)d_in[8];
    float* out = (float*)d_out;

    const int conv2_smem = (8 * C2PL + 2000) * 4;       // 54336 B
    const int fc1_smem   = (CK * 32 + BB * CK) * 4;     // 19968 B
    cudaFuncSetAttribute(conv2_pool_kernel,
                         cudaFuncAttributeMaxDynamicSharedMemorySize, conv2_smem);

    conv1_pool_kernel<<<dim3(7, 7, BB), dim3(8, 16)>>>(in, c1w, c1b);
    conv2_pool_kernel<<<dim3(2, 7, BB), dim3(16, 8), conv2_smem>>>(c2w, c2b);
    fc1_gemm_kernel<<<NCHUNK, 256, fc1_smem>>>(f1w);
    fc2_kernel<<<BB, 1024>>>(f1b, f2w, f2b);
    sampler_kernel<<<(BB * HH * WW) / 256, 256>>>(in, out);
}